// round 15
// baseline (speedup 1.0000x reference)
#include <cuda_runtime.h>
#include <cuda_bf16.h>
#include <math.h>
#include <stdint.h>

// Problem constants
#define NN 100000
#define IN_DIM 500
#define HID 128
#define OUTD 40
#define MAXE 1700000

// ---------------- scratch (device globals; allocation-free rule) -------------
__device__ int   g_stride;                 // 1 = int32 edges, 2 = int64 edges
__device__ int   g_cnt   [NN];
__device__ int   g_rowptr[NN + 1];
__device__ int   g_cursor[NN];
__device__ int   g_csrc  [MAXE];           // CSR: src per in-edge, binned by dst
__device__ float g_dinv  [NN];
__device__ __align__(16) __nv_bfloat16 g_h1b[(size_t)NN * HID];   // dinv*gemm1 out (bf16)
__device__ __align__(16) float         g_hr [(size_t)NN * HID];   // relu(agg1 + b1) fp32
__device__ __align__(16) __nv_bfloat16 g_h2b[(size_t)NN * OUTD];  // dinv*gemm2 out (bf16)
__device__ __align__(16) float         g_agg2[(size_t)NN * OUTD]; // agg2 (pre-bias)

// ---------------- init: dtype detect + zero counters -------------------------
__global__ void k_init(const int* __restrict__ e, int n) {
    int i = blockIdx.x * blockDim.x + threadIdx.x;
    if (i == 0) {
        int o = 0;
        #pragma unroll
        for (int q = 0; q < 8; q++) o |= e[2 * q + 1];   // high words if int64
        g_stride = (o == 0) ? 2 : 1;
    }
    if (i < n) g_cnt[i] = 0;
}

__global__ void k_degcount(const int* __restrict__ e, int E) {
    int i = blockIdx.x * blockDim.x + threadIdx.x;
    if (i >= E) return;
    int st = g_stride;
    int dst = e[(size_t)(E + i) * st];
    atomicAdd(&g_cnt[dst], 1);
}

// single-block exclusive scan of g_cnt -> rowptr/cursor, fused dinv.
#define SCAN_T 1024
__global__ __launch_bounds__(SCAN_T)
void k_scan(int n) {
    __shared__ int wsum[32];
    int t = threadIdx.x;
    int lane = t & 31, wid = t >> 5;
    int chunk = (n + SCAN_T - 1) / SCAN_T;
    int beg = t * chunk;
    int end = min(n, beg + chunk);

    int s = 0;
    int i = beg;
    for (; i + 4 <= end; i += 4) {
        int c0 = g_cnt[i], c1 = g_cnt[i + 1], c2 = g_cnt[i + 2], c3 = g_cnt[i + 3];
        s += c0 + c1 + c2 + c3;
    }
    for (; i < end; i++) s += g_cnt[i];

    int v = s;
    #pragma unroll
    for (int o = 1; o < 32; o <<= 1) {
        int u = __shfl_up_sync(0xffffffffu, v, o);
        if (lane >= o) v += u;
    }
    if (lane == 31) wsum[wid] = v;
    __syncthreads();
    if (wid == 0) {
        int w = wsum[lane];
        #pragma unroll
        for (int o = 1; o < 32; o <<= 1) {
            int u = __shfl_up_sync(0xffffffffu, w, o);
            if (lane >= o) w += u;
        }
        wsum[lane] = w;
    }
    __syncthreads();
    int warp_off = (wid == 0) ? 0 : wsum[wid - 1];
    int run = warp_off + (v - s);

    i = beg;
    for (; i + 4 <= end; i += 4) {
        int c0 = g_cnt[i], c1 = g_cnt[i + 1], c2 = g_cnt[i + 2], c3 = g_cnt[i + 3];
        g_rowptr[i] = run; g_cursor[i] = run;
        g_dinv[i] = rsqrtf((float)(c0 + 1)); run += c0;
        g_rowptr[i + 1] = run; g_cursor[i + 1] = run;
        g_dinv[i + 1] = rsqrtf((float)(c1 + 1)); run += c1;
        g_rowptr[i + 2] = run; g_cursor[i + 2] = run;
        g_dinv[i + 2] = rsqrtf((float)(c2 + 1)); run += c2;
        g_rowptr[i + 3] = run; g_cursor[i + 3] = run;
        g_dinv[i + 3] = rsqrtf((float)(c3 + 1)); run += c3;
    }
    for (; i < end; i++) {
        int c = g_cnt[i];
        g_rowptr[i] = run; g_cursor[i] = run;
        g_dinv[i] = rsqrtf((float)(c + 1)); run += c;
    }
    if (t == SCAN_T - 1) g_rowptr[n] = run;
}

__global__ void k_binedges(const int* __restrict__ e, int E) {
    int i = blockIdx.x * blockDim.x + threadIdx.x;
    if (i >= E) return;
    int st = g_stride;
    int src = e[(size_t)i * st];
    int dst = e[(size_t)(E + i) * st];
    int pos = atomicAdd(&g_cursor[dst], 1);
    g_csrc[pos] = src;
}

// ---------------- mma helpers -------------------------------------------------
__device__ __forceinline__ float to_tf32(float x) {
    float r;
    asm("cvt.rna.tf32.f32 %0, %1;" : "=f"(r) : "f"(x));
    return r;
}

__device__ __forceinline__ void mma_tf32(float c[4], const uint32_t a[4], const uint32_t b[2]) {
    asm volatile(
        "mma.sync.aligned.m16n8k8.row.col.f32.tf32.tf32.f32 "
        "{%0,%1,%2,%3}, {%4,%5,%6,%7}, {%8,%9}, {%0,%1,%2,%3};"
        : "+f"(c[0]), "+f"(c[1]), "+f"(c[2]), "+f"(c[3])
        : "r"(a[0]), "r"(a[1]), "r"(a[2]), "r"(a[3]), "r"(b[0]), "r"(b[1]));
}

__device__ __forceinline__ void mma_bf16(float c[4], const uint32_t a[4], const uint32_t b[2]) {
    asm volatile(
        "mma.sync.aligned.m16n8k16.row.col.f32.bf16.bf16.f32 "
        "{%0,%1,%2,%3}, {%4,%5,%6,%7}, {%8,%9}, {%0,%1,%2,%3};"
        : "+f"(c[0]), "+f"(c[1]), "+f"(c[2]), "+f"(c[3])
        : "r"(a[0]), "r"(a[1]), "r"(a[2]), "r"(a[3]), "r"(b[0]), "r"(b[1]));
}

__device__ __forceinline__ uint32_t pack_bf2(float x, float y) {
    __nv_bfloat162 p = __float22bfloat162_rn(make_float2(x, y));
    return *reinterpret_cast<uint32_t*>(&p);
}

__device__ __forceinline__ void ldsm_x4(uint32_t r[4], uint32_t smem_addr) {
    asm volatile(
        "ldmatrix.sync.aligned.m8n8.x4.shared.b16 {%0,%1,%2,%3}, [%4];"
        : "=r"(r[0]), "=r"(r[1]), "=r"(r[2]), "=r"(r[3]) : "r"(smem_addr));
}

__device__ __forceinline__ void ldsm_x4_trans(uint32_t r[4], uint32_t smem_addr) {
    asm volatile(
        "ldmatrix.sync.aligned.m8n8.x4.trans.shared.b16 {%0,%1,%2,%3}, [%4];"
        : "=r"(r[0]), "=r"(r[1]), "=r"(r[2]), "=r"(r[3]) : "r"(smem_addr));
}

// ---------------- GEMM1 (bf16 + ldmatrix): h1b = dinv * (x @ W1) -------------
#define BK1 32
#define APAD 40
#define BPAD 136
#define KT1 ((IN_DIM + BK1 - 1) / BK1)   // 16

__global__ __launch_bounds__(256, 2)
void k_gemm1_bf(const float* __restrict__ A, const float* __restrict__ B, int M) {
    __shared__ __nv_bfloat16 As[2][128][APAD];
    __shared__ __nv_bfloat16 Bs[2][BK1][BPAD];

    const int tid = threadIdx.x;
    const int lane = tid & 31;
    const int wid = tid >> 5;
    const int g = lane >> 2;
    const int tig = lane & 3;
    const int rb = (wid >> 1) * 32;
    const int nb = (wid & 1) * 64;
    const int blockRow = blockIdx.x * 128;

    float c[2][8][4];
    #pragma unroll
    for (int mt = 0; mt < 2; mt++)
        #pragma unroll
        for (int nt = 0; nt < 8; nt++)
            #pragma unroll
            for (int r = 0; r < 4; r++) c[mt][nt][r] = 0.f;

    const int ar = tid >> 1;
    const int ak = (tid & 1) * 16;
    const int bk = tid >> 3;
    const int bn = (tid & 7) * 16;

    float4 vA[4], vB[4];

    auto load_tiles = [&](int kt) {
        int grow = blockRow + ar;
        #pragma unroll
        for (int j = 0; j < 4; j++) {
            int k0 = kt + ak + j * 4;
            float4 v = make_float4(0.f, 0.f, 0.f, 0.f);
            if (grow < M && k0 + 4 <= IN_DIM)
                v = *reinterpret_cast<const float4*>(A + (size_t)grow * IN_DIM + k0);
            vA[j] = v;
        }
        int gk = kt + bk;
        #pragma unroll
        for (int j = 0; j < 4; j++) {
            float4 w = make_float4(0.f, 0.f, 0.f, 0.f);
            if (gk < IN_DIM)
                w = *reinterpret_cast<const float4*>(B + (size_t)gk * HID + bn + j * 4);
            vB[j] = w;
        }
    };

    auto store_tiles = [&](int buf) {
        #pragma unroll
        for (int j = 0; j < 4; j++) {
            uint2 pk = make_uint2(pack_bf2(vA[j].x, vA[j].y), pack_bf2(vA[j].z, vA[j].w));
            *reinterpret_cast<uint2*>(&As[buf][ar][ak + j * 4]) = pk;
        }
        #pragma unroll
        for (int j = 0; j < 4; j++) {
            uint2 pk = make_uint2(pack_bf2(vB[j].x, vB[j].y), pack_bf2(vB[j].z, vB[j].w));
            *reinterpret_cast<uint2*>(&Bs[buf][bk][bn + j * 4]) = pk;
        }
    };

    load_tiles(0);
    store_tiles(0);
    __syncthreads();

    const int amat = lane >> 3;
    const int a_row_off = (amat & 1) * 8 + (lane & 7);
    const int a_k_off = (amat >> 1) * 8;
    const int b_k_off = (amat & 1) * 8 + (lane & 7);
    const int b_n_off = (amat >> 1) * 8;

    int buf = 0;
    for (int it = 0; it < KT1; it++) {
        if (it + 1 < KT1) load_tiles((it + 1) * BK1);

        #pragma unroll
        for (int ks = 0; ks < 2; ks++) {
            const int kb = ks * 16;
            uint32_t af[2][4], bf[8][2];
            #pragma unroll
            for (int mt = 0; mt < 2; mt++) {
                uint32_t addr = (uint32_t)__cvta_generic_to_shared(
                    &As[buf][rb + mt * 16 + a_row_off][kb + a_k_off]);
                ldsm_x4(af[mt], addr);
            }
            #pragma unroll
            for (int jp = 0; jp < 4; jp++) {
                uint32_t r[4];
                uint32_t addr = (uint32_t)__cvta_generic_to_shared(
                    &Bs[buf][kb + b_k_off][nb + jp * 16 + b_n_off]);
                ldsm_x4_trans(r, addr);
                bf[2 * jp][0] = r[0]; bf[2 * jp][1] = r[1];
                bf[2 * jp + 1][0] = r[2]; bf[2 * jp + 1][1] = r[3];
            }
            #pragma unroll
            for (int mt = 0; mt < 2; mt++)
                #pragma unroll
                for (int nt = 0; nt < 8; nt++)
                    mma_bf16(c[mt][nt], af[mt], bf[nt]);
        }

        if (it + 1 < KT1) store_tiles(buf ^ 1);
        __syncthreads();
        buf ^= 1;
    }

    // epilogue: pre-scale by dinv[row], bf16 stores
    #pragma unroll
    for (int mt = 0; mt < 2; mt++) {
        int r0 = blockRow + rb + mt * 16 + g;
        int r1 = r0 + 8;
        float d0 = (r0 < M) ? g_dinv[r0] : 0.f;
        float d1 = (r1 < M) ? g_dinv[r1] : 0.f;
        #pragma unroll
        for (int nt = 0; nt < 8; nt++) {
            int col = nb + nt * 8 + 2 * tig;
            if (r0 < M)
                *reinterpret_cast<uint32_t*>(g_h1b + (size_t)r0 * HID + col) =
                    pack_bf2(c[mt][nt][0] * d0, c[mt][nt][1] * d0);
            if (r1 < M)
                *reinterpret_cast<uint32_t*>(g_h1b + (size_t)r1 * HID + col) =
                    pack_bf2(c[mt][nt][2] * d1, c[mt][nt][3] * d1);
        }
    }
}

// ------- fused layer-1 aggregate: pre-scaled rows, csrc software-pipelined ---
// agg = (sum_src row[s] + row[node]) * dinv[node] + b ; relu. (rows carry dinv[src])
__device__ __forceinline__ void bf4_acc(float4& acc, uint2 raw) {
    __nv_bfloat162 p0 = *reinterpret_cast<__nv_bfloat162*>(&raw.x);
    __nv_bfloat162 p1 = *reinterpret_cast<__nv_bfloat162*>(&raw.y);
    float2 f0 = __bfloat1622float2(p0);
    float2 f1 = __bfloat1622float2(p1);
    acc.x += f0.x; acc.y += f0.y;
    acc.z += f1.x; acc.w += f1.y;
}

__global__ __launch_bounds__(256)
void k_gather1(const float* __restrict__ b1, int N) {
    int node = (blockIdx.x * blockDim.x + threadIdx.x) >> 5;
    int lane = threadIdx.x & 31;
    if (node >= N) return;
    float dd = g_dinv[node];
    int p   = g_rowptr[node];
    int end = g_rowptr[node + 1];
    float4 acc = make_float4(0.f, 0.f, 0.f, 0.f);

    int s[8];
    #pragma unroll
    for (int q = 0; q < 8; q++) s[q] = (p + q < end) ? g_csrc[p + q] : -1;

    for (int base = p; base < end; base += 8) {
        uint2 v[8];
        #pragma unroll
        for (int q = 0; q < 8; q++)
            v[q] = (s[q] >= 0) ? reinterpret_cast<const uint2*>(g_h1b + (size_t)s[q] * HID)[lane]
                               : make_uint2(0u, 0u);
        int nb = base + 8;
        int s2[8];
        #pragma unroll
        for (int q = 0; q < 8; q++) s2[q] = (nb + q < end) ? g_csrc[nb + q] : -1;
        #pragma unroll
        for (int q = 0; q < 8; q++) bf4_acc(acc, v[q]);
        #pragma unroll
        for (int q = 0; q < 8; q++) s[q] = s2[q];
    }

    // self row is pre-scaled by dd already
    bf4_acc(acc, reinterpret_cast<const uint2*>(g_h1b + (size_t)node * HID)[lane]);
    float4 b = reinterpret_cast<const float4*>(b1)[lane];
    float4 r;
    r.x = fmaxf(acc.x * dd + b.x, 0.f);
    r.y = fmaxf(acc.y * dd + b.y, 0.f);
    r.z = fmaxf(acc.z * dd + b.z, 0.f);
    r.w = fmaxf(acc.w * dd + b.w, 0.f);
    reinterpret_cast<float4*>(g_hr + (size_t)node * HID)[lane] = r;
}

// ---------------- GEMM2 (tf32): h2b = dinv * (hr @ W2) (bf16 out) ------------
#define G2_HS 36
__global__ __launch_bounds__(256)
void k_gemm2_tc(const float* __restrict__ W2, int M) {
    __shared__ __align__(16) float sH[128][G2_HS];
    __shared__ __align__(16) float sW[HID][OUTD];

    const int tid = threadIdx.x;
    const int lane = tid & 31;
    const int wid = tid >> 5;
    const int g = lane >> 2;
    const int tig = lane & 3;
    const int blockRow = blockIdx.x * 128;

    #pragma unroll
    for (int i = 0; i < 5; i++) {
        int f = tid + 256 * i;
        int r = f / 10, q = f - r * 10;
        float4 w = *reinterpret_cast<const float4*>(W2 + r * OUTD + q * 4);
        w.x = to_tf32(w.x); w.y = to_tf32(w.y); w.z = to_tf32(w.z); w.w = to_tf32(w.w);
        *reinterpret_cast<float4*>(&sW[r][q * 4]) = w;
    }

    float c[5][4];
    #pragma unroll
    for (int nt = 0; nt < 5; nt++)
        #pragma unroll
        for (int r = 0; r < 4; r++) c[nt][r] = 0.f;

    for (int chunk = 0; chunk < 4; chunk++) {
        #pragma unroll
        for (int i = 0; i < 4; i++) {
            int f = tid + 256 * i;
            int row = f >> 3, q = f & 7;
            int gr = blockRow + row;
            float4 v = make_float4(0.f, 0.f, 0.f, 0.f);
            if (gr < M)
                v = *reinterpret_cast<const float4*>(g_hr + (size_t)gr * HID + chunk * 32 + q * 4);
            v.x = to_tf32(v.x); v.y = to_tf32(v.y); v.z = to_tf32(v.z); v.w = to_tf32(v.w);
            *reinterpret_cast<float4*>(&sH[row][q * 4]) = v;
        }
        __syncthreads();

        #pragma unroll
        for (int ks = 0; ks < 4; ks++) {
            const int k0 = ks * 8;
            const int r = wid * 16 + g;
            uint32_t af[4], bf[5][2];
            af[0] = __float_as_uint(sH[r    ][k0 + tig]);
            af[1] = __float_as_uint(sH[r + 8][k0 + tig]);
            af[2] = __float_as_uint(sH[r    ][k0 + tig + 4]);
            af[3] = __float_as_uint(sH[r + 8][k0 + tig + 4]);
            const int kk = chunk * 32 + k0;
            #pragma unroll
            for (int nt = 0; nt < 5; nt++) {
                int col = nt * 8 + g;
                bf[nt][0] = __float_as_uint(sW[kk + tig    ][col]);
                bf[nt][1] = __float_as_uint(sW[kk + tig + 4][col]);
            }
            #pragma unroll
            for (int nt = 0; nt < 5; nt++)
                mma_tf32(c[nt], af, bf[nt]);
        }
        __syncthreads();
    }

    int r0 = blockRow + wid * 16 + g;
    int r1 = r0 + 8;
    float d0 = (r0 < M) ? g_dinv[r0] : 0.f;
    float d1 = (r1 < M) ? g_dinv[r1] : 0.f;
    #pragma unroll
    for (int nt = 0; nt < 5; nt++) {
        int col = nt * 8 + tig * 2;
        if (r0 < M)
            *reinterpret_cast<uint32_t*>(g_h2b + (size_t)r0 * OUTD + col) =
                pack_bf2(c[nt][0] * d0, c[nt][1] * d0);
        if (r1 < M)
            *reinterpret_cast<uint32_t*>(g_h2b + (size_t)r1 * OUTD + col) =
                pack_bf2(c[nt][2] * d1, c[nt][3] * d1);
    }
}

// ------- fused layer-2 aggregate: warp/node, halfwarp/edge, prefetched -------
__global__ __launch_bounds__(256)
void k_gather2(int N) {
    int node = (blockIdx.x * blockDim.x + threadIdx.x) >> 5;
    int lane = threadIdx.x & 31;
    if (node >= N) return;
    const int half = lane >> 4;
    const int sub = lane & 15;
    const bool act = sub < 10;

    float dd = g_dinv[node];
    int p   = g_rowptr[node];
    int end = g_rowptr[node + 1];

    float4 acc = make_float4(0.f, 0.f, 0.f, 0.f);

    int i0 = p + half;                 // this halfwarp's first edge (stride 2)
    int s[4];
    #pragma unroll
    for (int q = 0; q < 4; q++) {
        int idx = i0 + 2 * q;
        s[q] = (idx < end) ? g_csrc[idx] : -1;
    }

    for (int base = i0; base < end; base += 8) {
        uint2 v[4];
        #pragma unroll
        for (int q = 0; q < 4; q++)
            v[q] = (s[q] >= 0 && act)
                 ? reinterpret_cast<const uint2*>(g_h2b + (size_t)s[q] * OUTD)[sub]
                 : make_uint2(0u, 0u);
        int nb = base + 8;
        int s2[4];
        #pragma unroll
        for (int q = 0; q < 4; q++) {
            int idx = nb + 2 * q;
            s2[q] = (idx < end) ? g_csrc[idx] : -1;
        }
        #pragma unroll
        for (int q = 0; q < 4; q++) bf4_acc(acc, v[q]);
        #pragma unroll
        for (int q = 0; q < 4; q++) s[q] = s2[q];
    }

    acc.x += __shfl_xor_sync(0xffffffffu, acc.x, 16);
    acc.y += __shfl_xor_sync(0xffffffffu, acc.y, 16);
    acc.z += __shfl_xor_sync(0xffffffffu, acc.z, 16);
    acc.w += __shfl_xor_sync(0xffffffffu, acc.w, 16);

    if (half == 0 && act) {
        bf4_acc(acc, reinterpret_cast<const uint2*>(g_h2b + (size_t)node * OUTD)[sub]);
        float4 r;
        r.x = acc.x * dd;
        r.y = acc.y * dd;
        r.z = acc.z * dd;
        r.w = acc.w * dd;
        reinterpret_cast<float4*>(g_agg2 + (size_t)node * OUTD)[sub] = r;
    }
}

// ---------------- bias + log_softmax: warp per row ---------------------------
__global__ __launch_bounds__(256)
void k_lsm(const float* __restrict__ b2, float* __restrict__ out, int n) {
    int row = (blockIdx.x * blockDim.x + threadIdx.x) >> 5;
    int lane = threadIdx.x & 31;
    if (row >= n) return;
    const float* a = g_agg2 + (size_t)row * OUTD;
    float v0 = a[lane] + b2[lane];
    float v1 = (lane < 8) ? (a[lane + 32] + b2[lane + 32]) : -INFINITY;
    float m = fmaxf(v0, v1);
    #pragma unroll
    for (int o = 16; o; o >>= 1) m = fmaxf(m, __shfl_xor_sync(0xffffffffu, m, o));
    float s = expf(v0 - m) + ((lane < 8) ? expf(v1 - m) : 0.f);
    #pragma unroll
    for (int o = 16; o; o >>= 1) s += __shfl_xor_sync(0xffffffffu, s, o);
    float l = m + logf(s);
    out[(size_t)row * OUTD + lane] = v0 - l;
    if (lane < 8) out[(size_t)row * OUTD + 32 + lane] = v1 - l;
}

// ---------------- launch -----------------------------------------------------
// Pre-scaling makes gemm1 depend on dinv -> scan (3) precedes gemm1 (4, profiled).
extern "C" void kernel_launch(void* const* d_in, const int* in_sizes, int n_in,
                              void* d_out, int out_size) {
    const float* x  = (const float*)d_in[0];
    const int*   e  = (const int*)d_in[1];
    const float* W1 = (const float*)d_in[2];
    const float* b1 = (const float*)d_in[3];
    const float* W2 = (const float*)d_in[4];
    const float* b2 = (const float*)d_in[5];
    float* out = (float*)d_out;

    int N = in_sizes[0] / IN_DIM;     // 100000
    int E = in_sizes[1] / 2;          // 1600000

    k_init<<<(N + 255) / 256, 256>>>(e, N);                   // 1
    k_degcount<<<(E + 255) / 256, 256>>>(e, E);               // 2
    k_scan<<<1, SCAN_T>>>(N);                                 // 3
    k_gemm1_bf<<<(N + 127) / 128, 256>>>(x, W1, N);           // 4  <- profiled
    k_binedges<<<(E + 255) / 256, 256>>>(e, E);               // 5

    long long g1 = (long long)N * 32;
    k_gather1<<<(int)((g1 + 255) / 256), 256>>>(b1, N);       // 6

    k_gemm2_tc<<<(N + 127) / 128, 256>>>(W2, N);              // 7
    long long g2 = (long long)N * 32;
    k_gather2<<<(int)((g2 + 255) / 256), 256>>>(N);           // 8

    long long tl = (long long)N * 32;
    k_lsm<<<(int)((tl + 255) / 256), 256>>>(b2, out, N);      // 9
}

// round 16
// speedup vs baseline: 1.6511x; 1.6511x over previous
#include <cuda_runtime.h>
#include <cuda_bf16.h>
#include <math.h>
#include <stdint.h>

// Problem constants
#define NN 100000
#define IN_DIM 500
#define HID 128
#define OUTD 40
#define MAXE 1700000

// ---------------- scratch (device globals; allocation-free rule) -------------
__device__ int   g_stride;                 // 1 = int32 edges, 2 = int64 edges
__device__ int   g_cnt   [NN];
__device__ int   g_rowptr[NN + 1];
__device__ int   g_cursor[NN];
__device__ int   g_csrc  [MAXE];           // CSR: src per in-edge, binned by dst
__device__ float g_dinv  [NN];
__device__ __align__(16) __nv_bfloat16 g_h1b[(size_t)NN * HID];   // gemm1 out (bf16)
__device__ __align__(16) float         g_hr [(size_t)NN * HID];   // relu(agg1 + b1) fp32
__device__ __align__(16) __nv_bfloat16 g_h2b[(size_t)NN * OUTD];  // gemm2 out (bf16)
__device__ __align__(16) float         g_agg2[(size_t)NN * OUTD]; // agg2 (pre-bias)

// ---------------- init: dtype detect + zero counters -------------------------
__global__ void k_init(const int* __restrict__ e, int n) {
    int i = blockIdx.x * blockDim.x + threadIdx.x;
    if (i == 0) {
        int o = 0;
        #pragma unroll
        for (int q = 0; q < 8; q++) o |= e[2 * q + 1];   // high words if int64
        g_stride = (o == 0) ? 2 : 1;
    }
    if (i < n) g_cnt[i] = 0;
}

__global__ void k_degcount(const int* __restrict__ e, int E) {
    int i = blockIdx.x * blockDim.x + threadIdx.x;
    if (i >= E) return;
    int st = g_stride;
    int dst = e[(size_t)(E + i) * st];
    atomicAdd(&g_cnt[dst], 1);
}

// single-block exclusive scan of g_cnt -> rowptr/cursor, fused dinv.
#define SCAN_T 1024
__global__ __launch_bounds__(SCAN_T)
void k_scan(int n) {
    __shared__ int wsum[32];
    int t = threadIdx.x;
    int lane = t & 31, wid = t >> 5;
    int chunk = (n + SCAN_T - 1) / SCAN_T;
    int beg = t * chunk;
    int end = min(n, beg + chunk);

    int s = 0;
    int i = beg;
    for (; i + 4 <= end; i += 4) {
        int c0 = g_cnt[i], c1 = g_cnt[i + 1], c2 = g_cnt[i + 2], c3 = g_cnt[i + 3];
        s += c0 + c1 + c2 + c3;
    }
    for (; i < end; i++) s += g_cnt[i];

    int v = s;
    #pragma unroll
    for (int o = 1; o < 32; o <<= 1) {
        int u = __shfl_up_sync(0xffffffffu, v, o);
        if (lane >= o) v += u;
    }
    if (lane == 31) wsum[wid] = v;
    __syncthreads();
    if (wid == 0) {
        int w = wsum[lane];
        #pragma unroll
        for (int o = 1; o < 32; o <<= 1) {
            int u = __shfl_up_sync(0xffffffffu, w, o);
            if (lane >= o) w += u;
        }
        wsum[lane] = w;
    }
    __syncthreads();
    int warp_off = (wid == 0) ? 0 : wsum[wid - 1];
    int run = warp_off + (v - s);

    i = beg;
    for (; i + 4 <= end; i += 4) {
        int c0 = g_cnt[i], c1 = g_cnt[i + 1], c2 = g_cnt[i + 2], c3 = g_cnt[i + 3];
        g_rowptr[i] = run; g_cursor[i] = run;
        g_dinv[i] = rsqrtf((float)(c0 + 1)); run += c0;
        g_rowptr[i + 1] = run; g_cursor[i + 1] = run;
        g_dinv[i + 1] = rsqrtf((float)(c1 + 1)); run += c1;
        g_rowptr[i + 2] = run; g_cursor[i + 2] = run;
        g_dinv[i + 2] = rsqrtf((float)(c2 + 1)); run += c2;
        g_rowptr[i + 3] = run; g_cursor[i + 3] = run;
        g_dinv[i + 3] = rsqrtf((float)(c3 + 1)); run += c3;
    }
    for (; i < end; i++) {
        int c = g_cnt[i];
        g_rowptr[i] = run; g_cursor[i] = run;
        g_dinv[i] = rsqrtf((float)(c + 1)); run += c;
    }
    if (t == SCAN_T - 1) g_rowptr[n] = run;
}

__global__ void k_binedges(const int* __restrict__ e, int E) {
    int i = blockIdx.x * blockDim.x + threadIdx.x;
    if (i >= E) return;
    int st = g_stride;
    int src = e[(size_t)i * st];
    int dst = e[(size_t)(E + i) * st];
    int pos = atomicAdd(&g_cursor[dst], 1);
    g_csrc[pos] = src;
}

// ---------------- mma helpers -------------------------------------------------
__device__ __forceinline__ float to_tf32(float x) {
    float r;
    asm("cvt.rna.tf32.f32 %0, %1;" : "=f"(r) : "f"(x));
    return r;
}

__device__ __forceinline__ void mma_tf32(float c[4], const uint32_t a[4], const uint32_t b[2]) {
    asm volatile(
        "mma.sync.aligned.m16n8k8.row.col.f32.tf32.tf32.f32 "
        "{%0,%1,%2,%3}, {%4,%5,%6,%7}, {%8,%9}, {%0,%1,%2,%3};"
        : "+f"(c[0]), "+f"(c[1]), "+f"(c[2]), "+f"(c[3])
        : "r"(a[0]), "r"(a[1]), "r"(a[2]), "r"(a[3]), "r"(b[0]), "r"(b[1]));
}

__device__ __forceinline__ void mma_bf16(float c[4], const uint32_t a[4], const uint32_t b[2]) {
    asm volatile(
        "mma.sync.aligned.m16n8k16.row.col.f32.bf16.bf16.f32 "
        "{%0,%1,%2,%3}, {%4,%5,%6,%7}, {%8,%9}, {%0,%1,%2,%3};"
        : "+f"(c[0]), "+f"(c[1]), "+f"(c[2]), "+f"(c[3])
        : "r"(a[0]), "r"(a[1]), "r"(a[2]), "r"(a[3]), "r"(b[0]), "r"(b[1]));
}

__device__ __forceinline__ uint32_t pack_bf2(float x, float y) {
    __nv_bfloat162 p = __float22bfloat162_rn(make_float2(x, y));
    return *reinterpret_cast<uint32_t*>(&p);
}

__device__ __forceinline__ void ldsm_x4(uint32_t r[4], uint32_t smem_addr) {
    asm volatile(
        "ldmatrix.sync.aligned.m8n8.x4.shared.b16 {%0,%1,%2,%3}, [%4];"
        : "=r"(r[0]), "=r"(r[1]), "=r"(r[2]), "=r"(r[3]) : "r"(smem_addr));
}

__device__ __forceinline__ void ldsm_x4_trans(uint32_t r[4], uint32_t smem_addr) {
    asm volatile(
        "ldmatrix.sync.aligned.m8n8.x4.trans.shared.b16 {%0,%1,%2,%3}, [%4];"
        : "=r"(r[0]), "=r"(r[1]), "=r"(r[2]), "=r"(r[3]) : "r"(smem_addr));
}

// ---------------- GEMM1 (bf16 + ldmatrix): h1b = x @ W1 (bf16 out) -----------
#define BK1 32
#define APAD 40
#define BPAD 136
#define KT1 ((IN_DIM + BK1 - 1) / BK1)   // 16

__global__ __launch_bounds__(256, 2)
void k_gemm1_bf(const float* __restrict__ A, const float* __restrict__ B, int M) {
    __shared__ __nv_bfloat16 As[2][128][APAD];
    __shared__ __nv_bfloat16 Bs[2][BK1][BPAD];

    const int tid = threadIdx.x;
    const int lane = tid & 31;
    const int wid = tid >> 5;
    const int g = lane >> 2;
    const int tig = lane & 3;
    const int rb = (wid >> 1) * 32;
    const int nb = (wid & 1) * 64;
    const int blockRow = blockIdx.x * 128;

    float c[2][8][4];
    #pragma unroll
    for (int mt = 0; mt < 2; mt++)
        #pragma unroll
        for (int nt = 0; nt < 8; nt++)
            #pragma unroll
            for (int r = 0; r < 4; r++) c[mt][nt][r] = 0.f;

    const int ar = tid >> 1;
    const int ak = (tid & 1) * 16;
    const int bk = tid >> 3;
    const int bn = (tid & 7) * 16;

    float4 vA[4], vB[4];

    auto load_tiles = [&](int kt) {
        int grow = blockRow + ar;
        #pragma unroll
        for (int j = 0; j < 4; j++) {
            int k0 = kt + ak + j * 4;
            float4 v = make_float4(0.f, 0.f, 0.f, 0.f);
            if (grow < M && k0 + 4 <= IN_DIM)
                v = *reinterpret_cast<const float4*>(A + (size_t)grow * IN_DIM + k0);
            vA[j] = v;
        }
        int gk = kt + bk;
        #pragma unroll
        for (int j = 0; j < 4; j++) {
            float4 w = make_float4(0.f, 0.f, 0.f, 0.f);
            if (gk < IN_DIM)
                w = *reinterpret_cast<const float4*>(B + (size_t)gk * HID + bn + j * 4);
            vB[j] = w;
        }
    };

    auto store_tiles = [&](int buf) {
        #pragma unroll
        for (int j = 0; j < 4; j++) {
            uint2 pk = make_uint2(pack_bf2(vA[j].x, vA[j].y), pack_bf2(vA[j].z, vA[j].w));
            *reinterpret_cast<uint2*>(&As[buf][ar][ak + j * 4]) = pk;
        }
        #pragma unroll
        for (int j = 0; j < 4; j++) {
            uint2 pk = make_uint2(pack_bf2(vB[j].x, vB[j].y), pack_bf2(vB[j].z, vB[j].w));
            *reinterpret_cast<uint2*>(&Bs[buf][bk][bn + j * 4]) = pk;
        }
    };

    load_tiles(0);
    store_tiles(0);
    __syncthreads();

    const int amat = lane >> 3;
    const int a_row_off = (amat & 1) * 8 + (lane & 7);
    const int a_k_off = (amat >> 1) * 8;
    const int b_k_off = (amat & 1) * 8 + (lane & 7);
    const int b_n_off = (amat >> 1) * 8;

    int buf = 0;
    for (int it = 0; it < KT1; it++) {
        if (it + 1 < KT1) load_tiles((it + 1) * BK1);

        #pragma unroll
        for (int ks = 0; ks < 2; ks++) {
            const int kb = ks * 16;
            uint32_t af[2][4], bf[8][2];
            #pragma unroll
            for (int mt = 0; mt < 2; mt++) {
                uint32_t addr = (uint32_t)__cvta_generic_to_shared(
                    &As[buf][rb + mt * 16 + a_row_off][kb + a_k_off]);
                ldsm_x4(af[mt], addr);
            }
            #pragma unroll
            for (int jp = 0; jp < 4; jp++) {
                uint32_t r[4];
                uint32_t addr = (uint32_t)__cvta_generic_to_shared(
                    &Bs[buf][kb + b_k_off][nb + jp * 16 + b_n_off]);
                ldsm_x4_trans(r, addr);
                bf[2 * jp][0] = r[0]; bf[2 * jp][1] = r[1];
                bf[2 * jp + 1][0] = r[2]; bf[2 * jp + 1][1] = r[3];
            }
            #pragma unroll
            for (int mt = 0; mt < 2; mt++)
                #pragma unroll
                for (int nt = 0; nt < 8; nt++)
                    mma_bf16(c[mt][nt], af[mt], bf[nt]);
        }

        if (it + 1 < KT1) store_tiles(buf ^ 1);
        __syncthreads();
        buf ^= 1;
    }

    #pragma unroll
    for (int mt = 0; mt < 2; mt++) {
        int r0 = blockRow + rb + mt * 16 + g;
        int r1 = r0 + 8;
        #pragma unroll
        for (int nt = 0; nt < 8; nt++) {
            int col = nb + nt * 8 + 2 * tig;
            if (r0 < M)
                *reinterpret_cast<uint32_t*>(g_h1b + (size_t)r0 * HID + col) =
                    pack_bf2(c[mt][nt][0], c[mt][nt][1]);
            if (r1 < M)
                *reinterpret_cast<uint32_t*>(g_h1b + (size_t)r1 * HID + col) =
                    pack_bf2(c[mt][nt][2], c[mt][nt][3]);
        }
    }
}

// ------- fused layer-1 aggregate: warp per node, bf16 gather(batch 8) --------
__device__ __forceinline__ void bf4_fma(float4& acc, uint2 raw, float w) {
    __nv_bfloat162 p0 = *reinterpret_cast<__nv_bfloat162*>(&raw.x);
    __nv_bfloat162 p1 = *reinterpret_cast<__nv_bfloat162*>(&raw.y);
    float2 f0 = __bfloat1622float2(p0);
    float2 f1 = __bfloat1622float2(p1);
    acc.x += w * f0.x; acc.y += w * f0.y;
    acc.z += w * f1.x; acc.w += w * f1.y;
}

__global__ __launch_bounds__(256)
void k_gather1(const float* __restrict__ b1, int N) {
    int node = (blockIdx.x * blockDim.x + threadIdx.x) >> 5;
    int lane = threadIdx.x & 31;
    if (node >= N) return;
    float dd = g_dinv[node];
    int p   = g_rowptr[node];
    int end = g_rowptr[node + 1];
    float4 acc = make_float4(0.f, 0.f, 0.f, 0.f);

    for (; p + 8 <= end; p += 8) {
        int s[8]; float w[8]; uint2 v[8];
        #pragma unroll
        for (int q = 0; q < 8; q++) s[q] = g_csrc[p + q];
        #pragma unroll
        for (int q = 0; q < 8; q++) w[q] = g_dinv[s[q]];
        #pragma unroll
        for (int q = 0; q < 8; q++)
            v[q] = reinterpret_cast<const uint2*>(g_h1b + (size_t)s[q] * HID)[lane];
        #pragma unroll
        for (int q = 0; q < 8; q++) bf4_fma(acc, v[q], w[q]);
    }
    {
        int rem = end - p;
        int s[8]; float w[8]; uint2 v[8];
        #pragma unroll
        for (int q = 0; q < 8; q++) s[q] = (q < rem) ? g_csrc[p + q] : 0;
        #pragma unroll
        for (int q = 0; q < 8; q++) w[q] = (q < rem) ? g_dinv[s[q]] : 0.f;
        #pragma unroll
        for (int q = 0; q < 8; q++)
            v[q] = (q < rem) ? reinterpret_cast<const uint2*>(g_h1b + (size_t)s[q] * HID)[lane]
                             : make_uint2(0u, 0u);
        #pragma unroll
        for (int q = 0; q < 8; q++) bf4_fma(acc, v[q], w[q]);
    }

    float4 self = make_float4(0.f, 0.f, 0.f, 0.f);
    bf4_fma(self, reinterpret_cast<const uint2*>(g_h1b + (size_t)node * HID)[lane], 1.f);
    float sl = dd * dd;
    float4 b = reinterpret_cast<const float4*>(b1)[lane];
    float4 r;
    r.x = fmaxf(acc.x * dd + self.x * sl + b.x, 0.f);
    r.y = fmaxf(acc.y * dd + self.y * sl + b.y, 0.f);
    r.z = fmaxf(acc.z * dd + self.z * sl + b.z, 0.f);
    r.w = fmaxf(acc.w * dd + self.w * sl + b.w, 0.f);
    reinterpret_cast<float4*>(g_hr + (size_t)node * HID)[lane] = r;
}

// ---------------- GEMM2 (tf32 tensor cores): h2b = hr @ W2 (bf16 out) --------
#define G2_HS 36
__global__ __launch_bounds__(256)
void k_gemm2_tc(const float* __restrict__ W2, int M) {
    __shared__ __align__(16) float sH[128][G2_HS];
    __shared__ __align__(16) float sW[HID][OUTD];

    const int tid = threadIdx.x;
    const int lane = tid & 31;
    const int wid = tid >> 5;
    const int g = lane >> 2;
    const int tig = lane & 3;
    const int blockRow = blockIdx.x * 128;

    #pragma unroll
    for (int i = 0; i < 5; i++) {
        int f = tid + 256 * i;
        int r = f / 10, q = f - r * 10;
        float4 w = *reinterpret_cast<const float4*>(W2 + r * OUTD + q * 4);
        w.x = to_tf32(w.x); w.y = to_tf32(w.y); w.z = to_tf32(w.z); w.w = to_tf32(w.w);
        *reinterpret_cast<float4*>(&sW[r][q * 4]) = w;
    }

    float c[5][4];
    #pragma unroll
    for (int nt = 0; nt < 5; nt++)
        #pragma unroll
        for (int r = 0; r < 4; r++) c[nt][r] = 0.f;

    for (int chunk = 0; chunk < 4; chunk++) {
        #pragma unroll
        for (int i = 0; i < 4; i++) {
            int f = tid + 256 * i;
            int row = f >> 3, q = f & 7;
            int gr = blockRow + row;
            float4 v = make_float4(0.f, 0.f, 0.f, 0.f);
            if (gr < M)
                v = *reinterpret_cast<const float4*>(g_hr + (size_t)gr * HID + chunk * 32 + q * 4);
            v.x = to_tf32(v.x); v.y = to_tf32(v.y); v.z = to_tf32(v.z); v.w = to_tf32(v.w);
            *reinterpret_cast<float4*>(&sH[row][q * 4]) = v;
        }
        __syncthreads();

        #pragma unroll
        for (int ks = 0; ks < 4; ks++) {
            const int k0 = ks * 8;
            const int r = wid * 16 + g;
            uint32_t af[4], bf[5][2];
            af[0] = __float_as_uint(sH[r    ][k0 + tig]);
            af[1] = __float_as_uint(sH[r + 8][k0 + tig]);
            af[2] = __float_as_uint(sH[r    ][k0 + tig + 4]);
            af[3] = __float_as_uint(sH[r + 8][k0 + tig + 4]);
            const int kk = chunk * 32 + k0;
            #pragma unroll
            for (int nt = 0; nt < 5; nt++) {
                int col = nt * 8 + g;
                bf[nt][0] = __float_as_uint(sW[kk + tig    ][col]);
                bf[nt][1] = __float_as_uint(sW[kk + tig + 4][col]);
            }
            #pragma unroll
            for (int nt = 0; nt < 5; nt++)
                mma_tf32(c[nt], af, bf[nt]);
        }
        __syncthreads();
    }

    int r0 = blockRow + wid * 16 + g;
    int r1 = r0 + 8;
    #pragma unroll
    for (int nt = 0; nt < 5; nt++) {
        int col = nt * 8 + tig * 2;
        if (r0 < M)
            *reinterpret_cast<uint32_t*>(g_h2b + (size_t)r0 * OUTD + col) =
                pack_bf2(c[nt][0], c[nt][1]);
        if (r1 < M)
            *reinterpret_cast<uint32_t*>(g_h2b + (size_t)r1 * OUTD + col) =
                pack_bf2(c[nt][2], c[nt][3]);
    }
}

// ------- fused layer-2 aggregate: thread per (node, float4-group) ------------
__global__ __launch_bounds__(256)
void k_gather2(int N) {
    int idx = blockIdx.x * blockDim.x + threadIdx.x;
    if (idx >= N * 10) return;
    int node = idx / 10;
    int g = idx - node * 10;
    float dd = g_dinv[node];
    int p   = g_rowptr[node];
    int end = g_rowptr[node + 1];
    float4 acc = make_float4(0.f, 0.f, 0.f, 0.f);

    for (; p + 8 <= end; p += 8) {
        int s[8]; float w[8]; uint2 v[8];
        #pragma unroll
        for (int q = 0; q < 8; q++) s[q] = g_csrc[p + q];
        #pragma unroll
        for (int q = 0; q < 8; q++) w[q] = g_dinv[s[q]];
        #pragma unroll
        for (int q = 0; q < 8; q++)
            v[q] = reinterpret_cast<const uint2*>(g_h2b + (size_t)s[q] * OUTD)[g];
        #pragma unroll
        for (int q = 0; q < 8; q++) bf4_fma(acc, v[q], w[q]);
    }
    {
        int rem = end - p;
        int s[8]; float w[8]; uint2 v[8];
        #pragma unroll
        for (int q = 0; q < 8; q++) s[q] = (q < rem) ? g_csrc[p + q] : 0;
        #pragma unroll
        for (int q = 0; q < 8; q++) w[q] = (q < rem) ? g_dinv[s[q]] : 0.f;
        #pragma unroll
        for (int q = 0; q < 8; q++)
            v[q] = (q < rem) ? reinterpret_cast<const uint2*>(g_h2b + (size_t)s[q] * OUTD)[g]
                             : make_uint2(0u, 0u);
        #pragma unroll
        for (int q = 0; q < 8; q++) bf4_fma(acc, v[q], w[q]);
    }

    float4 self = make_float4(0.f, 0.f, 0.f, 0.f);
    bf4_fma(self, reinterpret_cast<const uint2*>(g_h2b + (size_t)node * OUTD)[g], 1.f);
    float sl = dd * dd;
    acc.x = acc.x * dd + self.x * sl;
    acc.y = acc.y * dd + self.y * sl;
    acc.z = acc.z * dd + self.z * sl;
    acc.w = acc.w * dd + self.w * sl;
    reinterpret_cast<float4*>(g_agg2 + (size_t)node * OUTD)[g] = acc;
}

// ---------------- bias + log_softmax: warp per row ---------------------------
__global__ __launch_bounds__(256)
void k_lsm(const float* __restrict__ b2, float* __restrict__ out, int n) {
    int row = (blockIdx.x * blockDim.x + threadIdx.x) >> 5;
    int lane = threadIdx.x & 31;
    if (row >= n) return;
    const float* a = g_agg2 + (size_t)row * OUTD;
    float v0 = a[lane] + b2[lane];
    float v1 = (lane < 8) ? (a[lane + 32] + b2[lane + 32]) : -INFINITY;
    float m = fmaxf(v0, v1);
    #pragma unroll
    for (int o = 16; o; o >>= 1) m = fmaxf(m, __shfl_xor_sync(0xffffffffu, m, o));
    float s = expf(v0 - m) + ((lane < 8) ? expf(v1 - m) : 0.f);
    #pragma unroll
    for (int o = 16; o; o >>= 1) s += __shfl_xor_sync(0xffffffffu, s, o);
    float l = m + logf(s);
    out[(size_t)row * OUTD + lane] = v0 - l;
    if (lane < 8) out[(size_t)row * OUTD + 32 + lane] = v1 - l;
}

// ---------------- launch -----------------------------------------------------
// Fork-join capture: gemm1 (needs only x,W1) runs on a side stream concurrently
// with the CSR build chain (init/degcount/scan/binedges, needs only e).
// gather1 joins both. Stream/event objects are host-side, created once outside
// capture; no device memory is allocated. Same launches every call.
extern "C" void kernel_launch(void* const* d_in, const int* in_sizes, int n_in,
                              void* d_out, int out_size) {
    const float* x  = (const float*)d_in[0];
    const int*   e  = (const int*)d_in[1];
    const float* W1 = (const float*)d_in[2];
    const float* b1 = (const float*)d_in[3];
    const float* W2 = (const float*)d_in[4];
    const float* b2 = (const float*)d_in[5];
    float* out = (float*)d_out;

    int N = in_sizes[0] / IN_DIM;     // 100000
    int E = in_sizes[1] / 2;          // 1600000

    static cudaStream_t s2 = nullptr;
    static cudaEvent_t ev_fork = nullptr, ev_join = nullptr;
    if (s2 == nullptr) {
        if (cudaStreamCreateWithFlags(&s2, cudaStreamNonBlocking) != cudaSuccess) s2 = nullptr;
        if (s2 && cudaEventCreateWithFlags(&ev_fork, cudaEventDisableTiming) != cudaSuccess) {
            cudaStreamDestroy(s2); s2 = nullptr;
        }
        if (s2 && cudaEventCreateWithFlags(&ev_join, cudaEventDisableTiming) != cudaSuccess) {
            cudaStreamDestroy(s2); s2 = nullptr;
        }
    }

    if (s2 != nullptr) {
        // fork: side stream runs gemm1 concurrently with CSR build
        cudaEventRecord(ev_fork, 0);
        cudaStreamWaitEvent(s2, ev_fork, 0);
        k_gemm1_bf<<<(N + 127) / 128, 256, 0, s2>>>(x, W1, N);
        cudaEventRecord(ev_join, s2);

        k_init<<<(N + 255) / 256, 256>>>(e, N);
        k_degcount<<<(E + 255) / 256, 256>>>(e, E);
        k_scan<<<1, SCAN_T>>>(N);
        k_binedges<<<(E + 255) / 256, 256>>>(e, E);

        cudaStreamWaitEvent(0, ev_join, 0);   // join before gather1
    } else {
        // fallback: serial order (identical semantics)
        k_init<<<(N + 255) / 256, 256>>>(e, N);
        k_degcount<<<(E + 255) / 256, 256>>>(e, E);
        k_scan<<<1, SCAN_T>>>(N);
        k_gemm1_bf<<<(N + 127) / 128, 256>>>(x, W1, N);
        k_binedges<<<(E + 255) / 256, 256>>>(e, E);
    }

    long long g1 = (long long)N * 32;
    k_gather1<<<(int)((g1 + 255) / 256), 256>>>(b1, N);

    k_gemm2_tc<<<(N + 127) / 128, 256>>>(W2, N);
    long long g2 = (long long)N * 10;
    k_gather2<<<(int)((g2 + 255) / 256), 256>>>(N);

    long long tl = (long long)N * 32;
    k_lsm<<<(int)((tl + 255) / 256), 256>>>(b2, out, N);
}

// round 17
// speedup vs baseline: 2.9789x; 1.8042x over previous
#include <cuda_runtime.h>
#include <cuda_bf16.h>
#include <math.h>
#include <stdint.h>

// Problem constants
#define NN 100000
#define IN_DIM 500
#define HID 128
#define OUTD 40
#define MAXE 1700000
#define SB 256
#define NBMAX ((NN + SB - 1) / SB)   // 391

// ---------------- scratch (device globals; allocation-free rule) -------------
__device__ int   g_stride;                 // 1 = int32 edges, 2 = int64 edges
__device__ int   g_cnt   [NN];
__device__ int   g_bsum  [NBMAX];
__device__ int   g_boff  [NBMAX];
__device__ int   g_rowptr[NN + 1];
__device__ int   g_cursor[NN];
__device__ int   g_csrc  [MAXE];           // CSR: src per in-edge, binned by dst
__device__ float g_dinv  [NN];
__device__ __align__(16) __nv_bfloat16 g_h1b[(size_t)NN * HID];   // gemm1 out (bf16)
__device__ __align__(16) float         g_hr [(size_t)NN * HID];   // relu(agg1 + b1) fp32
__device__ __align__(16) __nv_bfloat16 g_h2b[(size_t)NN * OUTD];  // gemm2 out (bf16)
__device__ __align__(16) float         g_agg2[(size_t)NN * OUTD]; // agg2 (pre-bias)

// ---------------- init: dtype detect + zero counters -------------------------
__global__ void k_init(const int* __restrict__ e, int n) {
    int i = blockIdx.x * blockDim.x + threadIdx.x;
    if (i == 0) {
        int o = 0;
        #pragma unroll
        for (int q = 0; q < 8; q++) o |= e[2 * q + 1];   // high words if int64
        g_stride = (o == 0) ? 2 : 1;
    }
    if (i < n) g_cnt[i] = 0;
}

__global__ void k_degcount(const int* __restrict__ e, int E) {
    int i = blockIdx.x * blockDim.x + threadIdx.x;
    if (i >= E) return;
    int st = g_stride;
    int dst = e[(size_t)(E + i) * st];
    atomicAdd(&g_cnt[dst], 1);
}

// ---------------- coalesced 3-phase scan -------------------------------------
// phase 1: per-block sums (coalesced)
__global__ __launch_bounds__(SB)
void k_partial(int n) {
    int b = blockIdx.x, t = threadIdx.x;
    int i = b * SB + t;
    int v = (i < n) ? g_cnt[i] : 0;
    #pragma unroll
    for (int o = 16; o; o >>= 1) v += __shfl_xor_sync(0xffffffffu, v, o);
    __shared__ int ws[SB / 32];
    if ((t & 31) == 0) ws[t >> 5] = v;
    __syncthreads();
    if (t == 0) {
        int s = 0;
        #pragma unroll
        for (int k = 0; k < SB / 32; k++) s += ws[k];
        g_bsum[b] = s;
    }
}

// phase 2: exclusive scan of block sums (single block, 512 thr covers 391)
__global__ __launch_bounds__(512)
void k_scanb(int nb, int n) {
    int t = threadIdx.x;
    int lane = t & 31, wid = t >> 5;
    int v = (t < nb) ? g_bsum[t] : 0;
    int x = v;
    #pragma unroll
    for (int o = 1; o < 32; o <<= 1) {
        int u = __shfl_up_sync(0xffffffffu, x, o);
        if (lane >= o) x += u;
    }
    __shared__ int ws[16];
    if (lane == 31) ws[wid] = x;
    __syncthreads();
    if (wid == 0) {
        int w = (lane < 16) ? ws[lane] : 0;
        #pragma unroll
        for (int o = 1; o < 16; o <<= 1) {
            int u = __shfl_up_sync(0xffffffffu, w, o);
            if (lane >= o) w += u;
        }
        if (lane < 16) ws[lane] = w;
    }
    __syncthreads();
    int incl = x + ((wid == 0) ? 0 : ws[wid - 1]);
    if (t < nb) g_boff[t] = incl - v;       // exclusive
    if (t == nb - 1) g_rowptr[n] = incl;    // total edges
}

// phase 3: block-local exclusive scan + block offset -> rowptr/cursor/dinv
__global__ __launch_bounds__(SB)
void k_fill(int n) {
    int b = blockIdx.x, t = threadIdx.x;
    int lane = t & 31, wid = t >> 5;
    int i = b * SB + t;
    int c = (i < n) ? g_cnt[i] : 0;
    int x = c;
    #pragma unroll
    for (int o = 1; o < 32; o <<= 1) {
        int u = __shfl_up_sync(0xffffffffu, x, o);
        if (lane >= o) x += u;
    }
    __shared__ int ws[SB / 32];
    if (lane == 31) ws[wid] = x;
    __syncthreads();
    if (wid == 0) {
        int w = (lane < SB / 32) ? ws[lane] : 0;
        #pragma unroll
        for (int o = 1; o < SB / 32; o <<= 1) {
            int u = __shfl_up_sync(0xffffffffu, w, o);
            if (lane >= o) w += u;
        }
        if (lane < SB / 32) ws[lane] = w;
    }
    __syncthreads();
    int excl = (x - c) + ((wid == 0) ? 0 : ws[wid - 1]) + g_boff[b];
    if (i < n) {
        g_rowptr[i] = excl;
        g_cursor[i] = excl;
        g_dinv[i] = rsqrtf((float)(c + 1));
    }
}

__global__ void k_binedges(const int* __restrict__ e, int E) {
    int i = blockIdx.x * blockDim.x + threadIdx.x;
    if (i >= E) return;
    int st = g_stride;
    int src = e[(size_t)i * st];
    int dst = e[(size_t)(E + i) * st];
    int pos = atomicAdd(&g_cursor[dst], 1);
    g_csrc[pos] = src;
}

// ---------------- mma helpers -------------------------------------------------
__device__ __forceinline__ float to_tf32(float x) {
    float r;
    asm("cvt.rna.tf32.f32 %0, %1;" : "=f"(r) : "f"(x));
    return r;
}

__device__ __forceinline__ void mma_tf32(float c[4], const uint32_t a[4], const uint32_t b[2]) {
    asm volatile(
        "mma.sync.aligned.m16n8k8.row.col.f32.tf32.tf32.f32 "
        "{%0,%1,%2,%3}, {%4,%5,%6,%7}, {%8,%9}, {%0,%1,%2,%3};"
        : "+f"(c[0]), "+f"(c[1]), "+f"(c[2]), "+f"(c[3])
        : "r"(a[0]), "r"(a[1]), "r"(a[2]), "r"(a[3]), "r"(b[0]), "r"(b[1]));
}

__device__ __forceinline__ void mma_bf16(float c[4], const uint32_t a[4], const uint32_t b[2]) {
    asm volatile(
        "mma.sync.aligned.m16n8k16.row.col.f32.bf16.bf16.f32 "
        "{%0,%1,%2,%3}, {%4,%5,%6,%7}, {%8,%9}, {%0,%1,%2,%3};"
        : "+f"(c[0]), "+f"(c[1]), "+f"(c[2]), "+f"(c[3])
        : "r"(a[0]), "r"(a[1]), "r"(a[2]), "r"(a[3]), "r"(b[0]), "r"(b[1]));
}

__device__ __forceinline__ uint32_t pack_bf2(float x, float y) {
    __nv_bfloat162 p = __float22bfloat162_rn(make_float2(x, y));
    return *reinterpret_cast<uint32_t*>(&p);
}

__device__ __forceinline__ void ldsm_x4(uint32_t r[4], uint32_t smem_addr) {
    asm volatile(
        "ldmatrix.sync.aligned.m8n8.x4.shared.b16 {%0,%1,%2,%3}, [%4];"
        : "=r"(r[0]), "=r"(r[1]), "=r"(r[2]), "=r"(r[3]) : "r"(smem_addr));
}

__device__ __forceinline__ void ldsm_x4_trans(uint32_t r[4], uint32_t smem_addr) {
    asm volatile(
        "ldmatrix.sync.aligned.m8n8.x4.trans.shared.b16 {%0,%1,%2,%3}, [%4];"
        : "=r"(r[0]), "=r"(r[1]), "=r"(r[2]), "=r"(r[3]) : "r"(smem_addr));
}

// ---------------- GEMM1 (bf16 + ldmatrix): h1b = x @ W1 (bf16 out) -----------
#define BK1 32
#define APAD 40
#define BPAD 136
#define KT1 ((IN_DIM + BK1 - 1) / BK1)   // 16

__global__ __launch_bounds__(256, 2)
void k_gemm1_bf(const float* __restrict__ A, const float* __restrict__ B, int M) {
    __shared__ __nv_bfloat16 As[2][128][APAD];
    __shared__ __nv_bfloat16 Bs[2][BK1][BPAD];

    const int tid = threadIdx.x;
    const int lane = tid & 31;
    const int wid = tid >> 5;
    const int g = lane >> 2;
    const int tig = lane & 3;
    const int rb = (wid >> 1) * 32;
    const int nb = (wid & 1) * 64;
    const int blockRow = blockIdx.x * 128;

    float c[2][8][4];
    #pragma unroll
    for (int mt = 0; mt < 2; mt++)
        #pragma unroll
        for (int nt = 0; nt < 8; nt++)
            #pragma unroll
            for (int r = 0; r < 4; r++) c[mt][nt][r] = 0.f;

    const int ar = tid >> 1;
    const int ak = (tid & 1) * 16;
    const int bk = tid >> 3;
    const int bn = (tid & 7) * 16;

    float4 vA[4], vB[4];

    auto load_tiles = [&](int kt) {
        int grow = blockRow + ar;
        #pragma unroll
        for (int j = 0; j < 4; j++) {
            int k0 = kt + ak + j * 4;
            float4 v = make_float4(0.f, 0.f, 0.f, 0.f);
            if (grow < M && k0 + 4 <= IN_DIM)
                v = *reinterpret_cast<const float4*>(A + (size_t)grow * IN_DIM + k0);
            vA[j] = v;
        }
        int gk = kt + bk;
        #pragma unroll
        for (int j = 0; j < 4; j++) {
            float4 w = make_float4(0.f, 0.f, 0.f, 0.f);
            if (gk < IN_DIM)
                w = *reinterpret_cast<const float4*>(B + (size_t)gk * HID + bn + j * 4);
            vB[j] = w;
        }
    };

    auto store_tiles = [&](int buf) {
        #pragma unroll
        for (int j = 0; j < 4; j++) {
            uint2 pk = make_uint2(pack_bf2(vA[j].x, vA[j].y), pack_bf2(vA[j].z, vA[j].w));
            *reinterpret_cast<uint2*>(&As[buf][ar][ak + j * 4]) = pk;
        }
        #pragma unroll
        for (int j = 0; j < 4; j++) {
            uint2 pk = make_uint2(pack_bf2(vB[j].x, vB[j].y), pack_bf2(vB[j].z, vB[j].w));
            *reinterpret_cast<uint2*>(&Bs[buf][bk][bn + j * 4]) = pk;
        }
    };

    load_tiles(0);
    store_tiles(0);
    __syncthreads();

    const int amat = lane >> 3;
    const int a_row_off = (amat & 1) * 8 + (lane & 7);
    const int a_k_off = (amat >> 1) * 8;
    const int b_k_off = (amat & 1) * 8 + (lane & 7);
    const int b_n_off = (amat >> 1) * 8;

    int buf = 0;
    for (int it = 0; it < KT1; it++) {
        if (it + 1 < KT1) load_tiles((it + 1) * BK1);

        #pragma unroll
        for (int ks = 0; ks < 2; ks++) {
            const int kb = ks * 16;
            uint32_t af[2][4], bf[8][2];
            #pragma unroll
            for (int mt = 0; mt < 2; mt++) {
                uint32_t addr = (uint32_t)__cvta_generic_to_shared(
                    &As[buf][rb + mt * 16 + a_row_off][kb + a_k_off]);
                ldsm_x4(af[mt], addr);
            }
            #pragma unroll
            for (int jp = 0; jp < 4; jp++) {
                uint32_t r[4];
                uint32_t addr = (uint32_t)__cvta_generic_to_shared(
                    &Bs[buf][kb + b_k_off][nb + jp * 16 + b_n_off]);
                ldsm_x4_trans(r, addr);
                bf[2 * jp][0] = r[0]; bf[2 * jp][1] = r[1];
                bf[2 * jp + 1][0] = r[2]; bf[2 * jp + 1][1] = r[3];
            }
            #pragma unroll
            for (int mt = 0; mt < 2; mt++)
                #pragma unroll
                for (int nt = 0; nt < 8; nt++)
                    mma_bf16(c[mt][nt], af[mt], bf[nt]);
        }

        if (it + 1 < KT1) store_tiles(buf ^ 1);
        __syncthreads();
        buf ^= 1;
    }

    #pragma unroll
    for (int mt = 0; mt < 2; mt++) {
        int r0 = blockRow + rb + mt * 16 + g;
        int r1 = r0 + 8;
        #pragma unroll
        for (int nt = 0; nt < 8; nt++) {
            int col = nb + nt * 8 + 2 * tig;
            if (r0 < M)
                *reinterpret_cast<uint32_t*>(g_h1b + (size_t)r0 * HID + col) =
                    pack_bf2(c[mt][nt][0], c[mt][nt][1]);
            if (r1 < M)
                *reinterpret_cast<uint32_t*>(g_h1b + (size_t)r1 * HID + col) =
                    pack_bf2(c[mt][nt][2], c[mt][nt][3]);
        }
    }
}

// ------- fused layer-1 aggregate: warp per node, bf16 gather(batch 8) --------
__device__ __forceinline__ void bf4_fma(float4& acc, uint2 raw, float w) {
    __nv_bfloat162 p0 = *reinterpret_cast<__nv_bfloat162*>(&raw.x);
    __nv_bfloat162 p1 = *reinterpret_cast<__nv_bfloat162*>(&raw.y);
    float2 f0 = __bfloat1622float2(p0);
    float2 f1 = __bfloat1622float2(p1);
    acc.x += w * f0.x; acc.y += w * f0.y;
    acc.z += w * f1.x; acc.w += w * f1.y;
}

__global__ __launch_bounds__(256)
void k_gather1(const float* __restrict__ b1, int N) {
    int node = (blockIdx.x * blockDim.x + threadIdx.x) >> 5;
    int lane = threadIdx.x & 31;
    if (node >= N) return;
    float dd = g_dinv[node];
    int p   = g_rowptr[node];
    int end = g_rowptr[node + 1];
    float4 acc = make_float4(0.f, 0.f, 0.f, 0.f);

    for (; p + 8 <= end; p += 8) {
        int s[8]; float w[8]; uint2 v[8];
        #pragma unroll
        for (int q = 0; q < 8; q++) s[q] = g_csrc[p + q];
        #pragma unroll
        for (int q = 0; q < 8; q++) w[q] = g_dinv[s[q]];
        #pragma unroll
        for (int q = 0; q < 8; q++)
            v[q] = reinterpret_cast<const uint2*>(g_h1b + (size_t)s[q] * HID)[lane];
        #pragma unroll
        for (int q = 0; q < 8; q++) bf4_fma(acc, v[q], w[q]);
    }
    {
        int rem = end - p;
        int s[8]; float w[8]; uint2 v[8];
        #pragma unroll
        for (int q = 0; q < 8; q++) s[q] = (q < rem) ? g_csrc[p + q] : 0;
        #pragma unroll
        for (int q = 0; q < 8; q++) w[q] = (q < rem) ? g_dinv[s[q]] : 0.f;
        #pragma unroll
        for (int q = 0; q < 8; q++)
            v[q] = (q < rem) ? reinterpret_cast<const uint2*>(g_h1b + (size_t)s[q] * HID)[lane]
                             : make_uint2(0u, 0u);
        #pragma unroll
        for (int q = 0; q < 8; q++) bf4_fma(acc, v[q], w[q]);
    }

    float4 self = make_float4(0.f, 0.f, 0.f, 0.f);
    bf4_fma(self, reinterpret_cast<const uint2*>(g_h1b + (size_t)node * HID)[lane], 1.f);
    float sl = dd * dd;
    float4 b = reinterpret_cast<const float4*>(b1)[lane];
    float4 r;
    r.x = fmaxf(acc.x * dd + self.x * sl + b.x, 0.f);
    r.y = fmaxf(acc.y * dd + self.y * sl + b.y, 0.f);
    r.z = fmaxf(acc.z * dd + self.z * sl + b.z, 0.f);
    r.w = fmaxf(acc.w * dd + self.w * sl + b.w, 0.f);
    reinterpret_cast<float4*>(g_hr + (size_t)node * HID)[lane] = r;
}

// ---------------- GEMM2 (tf32 tensor cores): h2b = hr @ W2 (bf16 out) --------
#define G2_HS 36
__global__ __launch_bounds__(256)
void k_gemm2_tc(const float* __restrict__ W2, int M) {
    __shared__ __align__(16) float sH[128][G2_HS];
    __shared__ __align__(16) float sW[HID][OUTD];

    const int tid = threadIdx.x;
    const int lane = tid & 31;
    const int wid = tid >> 5;
    const int g = lane >> 2;
    const int tig = lane & 3;
    const int blockRow = blockIdx.x * 128;

    #pragma unroll
    for (int i = 0; i < 5; i++) {
        int f = tid + 256 * i;
        int r = f / 10, q = f - r * 10;
        float4 w = *reinterpret_cast<const float4*>(W2 + r * OUTD + q * 4);
        w.x = to_tf32(w.x); w.y = to_tf32(w.y); w.z = to_tf32(w.z); w.w = to_tf32(w.w);
        *reinterpret_cast<float4*>(&sW[r][q * 4]) = w;
    }

    float c[5][4];
    #pragma unroll
    for (int nt = 0; nt < 5; nt++)
        #pragma unroll
        for (int r = 0; r < 4; r++) c[nt][r] = 0.f;

    for (int chunk = 0; chunk < 4; chunk++) {
        #pragma unroll
        for (int i = 0; i < 4; i++) {
            int f = tid + 256 * i;
            int row = f >> 3, q = f & 7;
            int gr = blockRow + row;
            float4 v = make_float4(0.f, 0.f, 0.f, 0.f);
            if (gr < M)
                v = *reinterpret_cast<const float4*>(g_hr + (size_t)gr * HID + chunk * 32 + q * 4);
            v.x = to_tf32(v.x); v.y = to_tf32(v.y); v.z = to_tf32(v.z); v.w = to_tf32(v.w);
            *reinterpret_cast<float4*>(&sH[row][q * 4]) = v;
        }
        __syncthreads();

        #pragma unroll
        for (int ks = 0; ks < 4; ks++) {
            const int k0 = ks * 8;
            const int r = wid * 16 + g;
            uint32_t af[4], bf[5][2];
            af[0] = __float_as_uint(sH[r    ][k0 + tig]);
            af[1] = __float_as_uint(sH[r + 8][k0 + tig]);
            af[2] = __float_as_uint(sH[r    ][k0 + tig + 4]);
            af[3] = __float_as_uint(sH[r + 8][k0 + tig + 4]);
            const int kk = chunk * 32 + k0;
            #pragma unroll
            for (int nt = 0; nt < 5; nt++) {
                int col = nt * 8 + g;
                bf[nt][0] = __float_as_uint(sW[kk + tig    ][col]);
                bf[nt][1] = __float_as_uint(sW[kk + tig + 4][col]);
            }
            #pragma unroll
            for (int nt = 0; nt < 5; nt++)
                mma_tf32(c[nt], af, bf[nt]);
        }
        __syncthreads();
    }

    int r0 = blockRow + wid * 16 + g;
    int r1 = r0 + 8;
    #pragma unroll
    for (int nt = 0; nt < 5; nt++) {
        int col = nt * 8 + tig * 2;
        if (r0 < M)
            *reinterpret_cast<uint32_t*>(g_h2b + (size_t)r0 * OUTD + col) =
                pack_bf2(c[nt][0], c[nt][1]);
        if (r1 < M)
            *reinterpret_cast<uint32_t*>(g_h2b + (size_t)r1 * OUTD + col) =
                pack_bf2(c[nt][2], c[nt][3]);
    }
}

// ------- fused layer-2 aggregate: thread per (node, float4-group) ------------
__global__ __launch_bounds__(256)
void k_gather2(int N) {
    int idx = blockIdx.x * blockDim.x + threadIdx.x;
    if (idx >= N * 10) return;
    int node = idx / 10;
    int g = idx - node * 10;
    float dd = g_dinv[node];
    int p   = g_rowptr[node];
    int end = g_rowptr[node + 1];
    float4 acc = make_float4(0.f, 0.f, 0.f, 0.f);

    for (; p + 8 <= end; p += 8) {
        int s[8]; float w[8]; uint2 v[8];
        #pragma unroll
        for (int q = 0; q < 8; q++) s[q] = g_csrc[p + q];
        #pragma unroll
        for (int q = 0; q < 8; q++) w[q] = g_dinv[s[q]];
        #pragma unroll
        for (int q = 0; q < 8; q++)
            v[q] = reinterpret_cast<const uint2*>(g_h2b + (size_t)s[q] * OUTD)[g];
        #pragma unroll
        for (int q = 0; q < 8; q++) bf4_fma(acc, v[q], w[q]);
    }
    {
        int rem = end - p;
        int s[8]; float w[8]; uint2 v[8];
        #pragma unroll
        for (int q = 0; q < 8; q++) s[q] = (q < rem) ? g_csrc[p + q] : 0;
        #pragma unroll
        for (int q = 0; q < 8; q++) w[q] = (q < rem) ? g_dinv[s[q]] : 0.f;
        #pragma unroll
        for (int q = 0; q < 8; q++)
            v[q] = (q < rem) ? reinterpret_cast<const uint2*>(g_h2b + (size_t)s[q] * OUTD)[g]
                             : make_uint2(0u, 0u);
        #pragma unroll
        for (int q = 0; q < 8; q++) bf4_fma(acc, v[q], w[q]);
    }

    float4 self = make_float4(0.f, 0.f, 0.f, 0.f);
    bf4_fma(self, reinterpret_cast<const uint2*>(g_h2b + (size_t)node * OUTD)[g], 1.f);
    float sl = dd * dd;
    acc.x = acc.x * dd + self.x * sl;
    acc.y = acc.y * dd + self.y * sl;
    acc.z = acc.z * dd + self.z * sl;
    acc.w = acc.w * dd + self.w * sl;
    reinterpret_cast<float4*>(g_agg2 + (size_t)node * OUTD)[g] = acc;
}

// ---------------- bias + log_softmax: warp per row ---------------------------
__global__ __launch_bounds__(256)
void k_lsm(const float* __restrict__ b2, float* __restrict__ out, int n) {
    int row = (blockIdx.x * blockDim.x + threadIdx.x) >> 5;
    int lane = threadIdx.x & 31;
    if (row >= n) return;
    const float* a = g_agg2 + (size_t)row * OUTD;
    float v0 = a[lane] + b2[lane];
    float v1 = (lane < 8) ? (a[lane + 32] + b2[lane + 32]) : -INFINITY;
    float m = fmaxf(v0, v1);
    #pragma unroll
    for (int o = 16; o; o >>= 1) m = fmaxf(m, __shfl_xor_sync(0xffffffffu, m, o));
    float s = expf(v0 - m) + ((lane < 8) ? expf(v1 - m) : 0.f);
    #pragma unroll
    for (int o = 16; o; o >>= 1) s += __shfl_xor_sync(0xffffffffu, s, o);
    float l = m + logf(s);
    out[(size_t)row * OUTD + lane] = v0 - l;
    if (lane < 8) out[(size_t)row * OUTD + 32 + lane] = v1 - l;
}

// ---------------- launch -----------------------------------------------------
// Fork-join: gemm1 on side stream overlaps CSR build (now coalesced 3-phase scan).
extern "C" void kernel_launch(void* const* d_in, const int* in_sizes, int n_in,
                              void* d_out, int out_size) {
    const float* x  = (const float*)d_in[0];
    const int*   e  = (const int*)d_in[1];
    const float* W1 = (const float*)d_in[2];
    const float* b1 = (const float*)d_in[3];
    const float* W2 = (const float*)d_in[4];
    const float* b2 = (const float*)d_in[5];
    float* out = (float*)d_out;

    int N = in_sizes[0] / IN_DIM;     // 100000
    int E = in_sizes[1] / 2;          // 1600000
    int NB = (N + SB - 1) / SB;       // 391

    static cudaStream_t s2 = nullptr;
    static cudaEvent_t ev_fork = nullptr, ev_join = nullptr;
    if (s2 == nullptr) {
        if (cudaStreamCreateWithFlags(&s2, cudaStreamNonBlocking) != cudaSuccess) s2 = nullptr;
        if (s2 && cudaEventCreateWithFlags(&ev_fork, cudaEventDisableTiming) != cudaSuccess) {
            cudaStreamDestroy(s2); s2 = nullptr;
        }
        if (s2 && cudaEventCreateWithFlags(&ev_join, cudaEventDisableTiming) != cudaSuccess) {
            cudaStreamDestroy(s2); s2 = nullptr;
        }
    }

    if (s2 != nullptr) {
        cudaEventRecord(ev_fork, 0);
        cudaStreamWaitEvent(s2, ev_fork, 0);
        k_gemm1_bf<<<(N + 127) / 128, 256, 0, s2>>>(x, W1, N);
        cudaEventRecord(ev_join, s2);

        k_init<<<(N + 255) / 256, 256>>>(e, N);
        k_degcount<<<(E + 255) / 256, 256>>>(e, E);
        k_partial<<<NB, SB>>>(N);
        k_scanb<<<1, 512>>>(NB, N);
        k_fill<<<NB, SB>>>(N);
        k_binedges<<<(E + 255) / 256, 256>>>(e, E);

        cudaStreamWaitEvent(0, ev_join, 0);
    } else {
        k_init<<<(N + 255) / 256, 256>>>(e, N);
        k_degcount<<<(E + 255) / 256, 256>>>(e, E);
        k_partial<<<NB, SB>>>(N);
        k_scanb<<<1, 512>>>(NB, N);
        k_fill<<<NB, SB>>>(N);
        k_gemm1_bf<<<(N + 127) / 128, 256>>>(x, W1, N);
        k_binedges<<<(E + 255) / 256, 256>>>(e, E);
    }

    long long g1 = (long long)N * 32;
    k_gather1<<<(int)((g1 + 255) / 256), 256>>>(b1, N);

    k_gemm2_tc<<<(N + 127) / 128, 256>>>(W2, N);
    long long g2 = (long long)N * 10;
    k_gather2<<<(int)((g2 + 255) / 256), 256>>>(N);

    long long tl = (long long)N * 32;
    k_lsm<<<(int)((tl + 255) / 256), 256>>>(b2, out, N);
}